// round 5
// baseline (speedup 1.0000x reference)
#include <cuda_runtime.h>
#include <cstdint>

#define N_NODES 100000
#define N_EDGES 3200000
#define E4 (N_EDGES / 4)

// Scratch (device globals — no allocation allowed)
__device__ float  g_deg[N_NODES];    // raw in-degree (no self-loop); memset to 0
__device__ float  g_dinv[N_NODES];
__device__ float2 g_xs[N_NODES];     // x[i] * dinv[i]
__device__ float2 g_agg1[N_NODES];
__device__ float2 g_ps[N_NODES];     // (h1@W2)[i] * dinv[i]
__device__ float2 g_agg2[N_NODES];

__device__ __forceinline__ void red_add_f2(float2* addr, float2 v) {
    asm volatile("red.global.add.v2.f32 [%0], {%1, %2};"
                 :: "l"(addr), "f"(v.x), "f"(v.y) : "memory");
}
__device__ __forceinline__ void red_add_f(float* addr, float v) {
    asm volatile("red.global.add.f32 [%0], %1;"
                 :: "l"(addr), "f"(v) : "memory");
}

// ---------------------------------------------------------------------------
// Degree: 4 edges/thread, int4 index load.
__global__ void k_degree(const int4* __restrict__ dst4) {
    int t = blockIdx.x * blockDim.x + threadIdx.x;
    if (t < E4) {
        int4 d = dst4[t];
        red_add_f(&g_deg[d.x], 1.0f);
        red_add_f(&g_deg[d.y], 1.0f);
        red_add_f(&g_deg[d.z], 1.0f);
        red_add_f(&g_deg[d.w], 1.0f);
    }
}

__global__ void k_pre1(const float2* __restrict__ x2) {
    int i = blockIdx.x * blockDim.x + threadIdx.x;
    if (i < N_NODES) {
        float di = rsqrtf(g_deg[i] + 1.0f);   // +1 self-loop
        g_dinv[i] = di;
        float2 xi = x2[i];
        float2 xs = make_float2(xi.x * di, xi.y * di);
        g_xs[i] = xs;
        g_agg1[i] = xs;                       // self-loop seed
    }
}

// Scatter: 4 edges/thread. Gathers batched before REDs for MLP=4.
__global__ void k_scatter1(const int4* __restrict__ src4,
                           const int4* __restrict__ dst4) {
    int t = blockIdx.x * blockDim.x + threadIdx.x;
    if (t < E4) {
        int4 s = src4[t];
        int4 d = dst4[t];
        float2 v0 = g_xs[s.x];
        float2 v1 = g_xs[s.y];
        float2 v2 = g_xs[s.z];
        float2 v3 = g_xs[s.w];
        red_add_f2(&g_agg1[d.x], v0);
        red_add_f2(&g_agg1[d.y], v1);
        red_add_f2(&g_agg1[d.z], v2);
        red_add_f2(&g_agg1[d.w], v3);
    }
}

__global__ void k_mid(const float* __restrict__ W1,   // [2,16]
                      const float* __restrict__ b1,   // [16]
                      const float* __restrict__ W2) { // [16,2]
    int i = blockIdx.x * blockDim.x + threadIdx.x;
    if (i >= N_NODES) return;
    float di = g_dinv[i];
    float2 t = g_agg1[i];
    float2 a = make_float2(t.x * di, t.y * di);
    float px = 0.0f, py = 0.0f;
#pragma unroll
    for (int j = 0; j < 16; j++) {
        float h = a.x * __ldg(&W1[j]) + a.y * __ldg(&W1[16 + j]) + __ldg(&b1[j]);
        h = fmaxf(h, 0.0f);
        px += h * __ldg(&W2[2 * j]);
        py += h * __ldg(&W2[2 * j + 1]);
    }
    float2 ps = make_float2(px * di, py * di);
    g_ps[i] = ps;
    g_agg2[i] = ps;                           // self-loop seed
}

__global__ void k_scatter2(const int4* __restrict__ src4,
                           const int4* __restrict__ dst4) {
    int t = blockIdx.x * blockDim.x + threadIdx.x;
    if (t < E4) {
        int4 s = src4[t];
        int4 d = dst4[t];
        float2 v0 = g_ps[s.x];
        float2 v1 = g_ps[s.y];
        float2 v2 = g_ps[s.z];
        float2 v3 = g_ps[s.w];
        red_add_f2(&g_agg2[d.x], v0);
        red_add_f2(&g_agg2[d.y], v1);
        red_add_f2(&g_agg2[d.z], v2);
        red_add_f2(&g_agg2[d.w], v3);
    }
}

__global__ void k_out(const float* __restrict__ b2, float2* __restrict__ out) {
    int i = blockIdx.x * blockDim.x + threadIdx.x;
    if (i >= N_NODES) return;
    float di = g_dinv[i];
    float2 t = g_agg2[i];
    float2 z = make_float2(t.x * di + __ldg(&b2[0]),
                           t.y * di + __ldg(&b2[1]));
    float m = fmaxf(z.x, z.y);
    float lse = m + logf(expf(z.x - m) + expf(z.y - m));
    out[i] = make_float2(z.x - lse, z.y - lse);
}

// ---------------------------------------------------------------------------
extern "C" void kernel_launch(void* const* d_in, const int* in_sizes, int n_in,
                              void* d_out, int out_size) {
    const float* x  = (const float*)d_in[0];   // [N,2]
    const int*   ei = (const int*)d_in[1];     // [2,E] int32
    const float* W1 = (const float*)d_in[2];
    const float* b1 = (const float*)d_in[3];
    const float* W2 = (const float*)d_in[4];
    const float* b2 = (const float*)d_in[5];
    float2* out = (float2*)d_out;

    const int4* src4 = (const int4*)ei;
    const int4* dst4 = (const int4*)(ei + N_EDGES);
    const float2* x2 = (const float2*)x;

    const int T = 256;
    const int gN  = (N_NODES + T - 1) / T;
    const int gE4 = (E4 + T - 1) / T;

    float* deg_addr = nullptr;
    cudaGetSymbolAddress((void**)&deg_addr, g_deg);
    cudaMemsetAsync(deg_addr, 0, N_NODES * sizeof(float));

    k_degree<<<gE4, T>>>(dst4);
    k_pre1<<<gN, T>>>(x2);
    k_scatter1<<<gE4, T>>>(src4, dst4);
    k_mid<<<gN, T>>>(W1, b1, W2);
    k_scatter2<<<gE4, T>>>(src4, dst4);
    k_out<<<gN, T>>>(b2, out);
}